// round 10
// baseline (speedup 1.0000x reference)
#include <cuda_runtime.h>
#include <math.h>

#define BB   32
#define LL   512
#define HH   512
#define DIN  832
#define G3   1536
#define DPOS 64

// ---------------- scratch (static device globals; no allocation) ----------------
__device__ float d_X[2][BB][LL][DIN];        // embedded inputs per side
__device__ float d_GI[4][BB][LL][G3];        // input-gate preactivations per chain (s*2+dir)
__device__ float d_Hb[2][4][BB][HH];         // double-buffered hidden state
__device__ float d_OUT[2][BB][LL][2*HH];     // encoder outputs (fwd | bwd un-reversed)
__device__ float d_SIM[BB][LL][LL];          // cosine similarity
__device__ float d_NORM[2][BB][LL];
__device__ float d_MS[2][BB][LL];            // row-max / col-max sims
__device__ float d_REL[2][BB][LL];           // pos - argmax

// ---------------- embedding concat ----------------
__global__ void embed_k(const int* __restrict__ w1, const int* __restrict__ w2,
                        const int* __restrict__ p1, const int* __restrict__ p2,
                        const int* __restrict__ tb1, const int* __restrict__ te1,
                        const int* __restrict__ tb2, const int* __restrict__ te2,
                        const float* __restrict__ ew, const float* __restrict__ ep,
                        const float* __restrict__ pe)
{
    int gid = blockIdx.x;               // 0 .. 2*B*L-1
    int s   = gid >> 14;
    int rem = gid & 16383;
    int b   = rem >> 9;
    int l   = rem & 511;
    const int* wp  = s ? w2  : w1;
    const int* pp  = s ? p2  : p1;
    const int* tbp = s ? tb2 : tb1;
    const int* tep = s ? te2 : te1;
    int wi = wp[b*LL + l];
    int pi = pp[b*LL + l];
    int tb = tbp[b*LL + l];
    int te = tep[b*LL + l];
    float* dst = &d_X[s][b][l][0];
    for (int d = threadIdx.x; d < DIN; d += blockDim.x) {
        float v;
        if      (d < 256) v = ew[wi*256 + d];
        else if (d < 512) v = ep[pi*256 + (d-256)];
        else if (d < 576) v = pe[l*DPOS      + (d-512)];
        else if (d < 640) v = pe[tb*DPOS     + (d-576)];
        else if (d < 704) v = pe[te*DPOS     + (d-640)];
        else if (d < 768) v = pe[(te-l)*DPOS + (d-704)];
        else              v = pe[(l-tb)*DPOS + (d-768)];
        dst[d] = v;
    }
}

// ---------------- input GEMM: GI[c][b][l][g] = X(row) . Wih[dir][g] + bih ----------------
__global__ void __launch_bounds__(256) gemm_gi_k(const float* __restrict__ Wih,
                                                 const float* __restrict__ bih,
                                                 const int* __restrict__ len1,
                                                 const int* __restrict__ len2)
{
    __shared__ float As[16][68];
    __shared__ float Bs[16][68];
    int sd  = blockIdx.z;
    int s   = sd >> 1, dir = sd & 1;
    int n0  = blockIdx.x * 64;
    int m0  = blockIdx.y * 64;
    int b   = m0 >> 9;
    int lenb = (s == 0 ? len1 : len2)[b];
    int t   = threadIdx.x;
    int lr  = t >> 2;                 // 0..63 row within tile
    int kq  = (t & 3) * 4;            // k offset within chunk
    int l   = (m0 & 511) + lr;
    int lp  = l;
    if (dir) lp = (l < lenb) ? (lenb - 1 - l) : l;   // backward: gather reversed row
    const float* Arow = &d_X[s][b][lp][0];
    const float* Brow = Wih + (size_t)(dir*G3 + n0 + lr) * DIN;
    int tx = t & 15, ty = t >> 4;
    float acc[4][4] = {};
    for (int k0 = 0; k0 < DIN; k0 += 16) {
        float4 av = *(const float4*)(Arow + k0 + kq);
        float4 bv = *(const float4*)(Brow + k0 + kq);
        As[kq+0][lr] = av.x; As[kq+1][lr] = av.y; As[kq+2][lr] = av.z; As[kq+3][lr] = av.w;
        Bs[kq+0][lr] = bv.x; Bs[kq+1][lr] = bv.y; Bs[kq+2][lr] = bv.z; Bs[kq+3][lr] = bv.w;
        __syncthreads();
#pragma unroll
        for (int k = 0; k < 16; k++) {
            float a[4], bb[4];
#pragma unroll
            for (int i = 0; i < 4; i++) a[i]  = As[k][ty*4 + i];
#pragma unroll
            for (int j = 0; j < 4; j++) bb[j] = Bs[k][tx*4 + j];
#pragma unroll
            for (int i = 0; i < 4; i++)
#pragma unroll
                for (int j = 0; j < 4; j++)
                    acc[i][j] += a[i] * bb[j];
        }
        __syncthreads();
    }
    int c = s*2 + dir;
#pragma unroll
    for (int i = 0; i < 4; i++) {
        int ll = (m0 & 511) + ty*4 + i;
#pragma unroll
        for (int j = 0; j < 4; j++) {
            int g = n0 + tx*4 + j;
            d_GI[c][b][ll][g] = acc[i][j] + bih[dir*G3 + g];
        }
    }
}

// ---------------- GRU recurrence step: all 4 chains, hidden tile TH=16 ----------------
#define TH 16
__global__ void __launch_bounds__(384) gru_step_k(int t, int par,
                                                  const float* __restrict__ Whh,
                                                  const float* __restrict__ bhh,
                                                  const int* __restrict__ len1,
                                                  const int* __restrict__ len2)
{
    __shared__ float w_s[48][65];
    __shared__ float h_s[64][36];
    __shared__ float gh_s[48][32];
    int c   = blockIdx.y;
    int s   = c >> 1, dir = c & 1;
    int jh0 = blockIdx.x * TH;
    int tid = threadIdx.x;
    int g_local = tid >> 3;          // 0..47 (r:0-15, z:16-31, n:32-47)
    int bq = tid & 7;                // 4 batches each
    int bbase = bq * 4;
    float a0 = 0.f, a1 = 0.f, a2 = 0.f, a3 = 0.f;
    int rr = tid >> 3;
    int kk = (tid & 7) * 8;
    int grow_ld = (rr/TH)*HH + jh0 + (rr%TH);
    const float* wsrc = Whh + (size_t)(dir*G3 + grow_ld) * HH + kk;
    for (int k0 = 0; k0 < HH; k0 += 64) {
        // load 48x64 Whh chunk
        {
            float4 v0 = *(const float4*)(wsrc + k0);
            float4 v1 = *(const float4*)(wsrc + k0 + 4);
            w_s[rr][kk+0] = v0.x; w_s[rr][kk+1] = v0.y; w_s[rr][kk+2] = v0.z; w_s[rr][kk+3] = v0.w;
            w_s[rr][kk+4] = v1.x; w_s[rr][kk+5] = v1.y; w_s[rr][kk+6] = v1.z; w_s[rr][kk+7] = v1.w;
        }
        // load 32x64 hidden chunk (transposed: h_s[k][b])
        for (int i = tid; i < 2048; i += 384) {
            int bb = i >> 6, k = i & 63;
            h_s[k][bb] = d_Hb[par][c][bb][k0 + k];
        }
        __syncthreads();
#pragma unroll 16
        for (int k = 0; k < 64; k++) {
            float w = w_s[g_local][k];
            float4 h4 = *(const float4*)&h_s[k][bbase];
            a0 += w * h4.x; a1 += w * h4.y; a2 += w * h4.z; a3 += w * h4.w;
        }
        __syncthreads();
    }
    gh_s[g_local][bbase+0] = a0;
    gh_s[g_local][bbase+1] = a1;
    gh_s[g_local][bbase+2] = a2;
    gh_s[g_local][bbase+3] = a3;
    __syncthreads();

    const int* lenp = (s == 0) ? len1 : len2;
    const float* bh = bhh + dir*G3;
    for (int i = tid; i < BB*TH; i += 384) {
        int b = i / TH, j = i % TH;
        float hr = gh_s[j][b]       + bh[jh0 + j];
        float hz = gh_s[TH+j][b]    + bh[HH + jh0 + j];
        float hn = gh_s[2*TH+j][b]  + bh[2*HH + jh0 + j];
        const float* gi = &d_GI[c][b][t][0];
        float ir  = gi[jh0 + j];
        float iz  = gi[HH + jh0 + j];
        float inn = gi[2*HH + jh0 + j];
        float r = 1.f / (1.f + expf(-(ir + hr)));
        float z = 1.f / (1.f + expf(-(iz + hz)));
        float n = tanhf(inn + r * hn);
        float hold = d_Hb[par][c][b][jh0 + j];
        float hc   = (1.f - z) * n + z * hold;
        int  lenb  = lenp[b];
        bool valid = (t < lenb);
        d_Hb[par ^ 1][c][b][jh0 + j] = valid ? hc : hold;
        float outv = valid ? hc : 0.f;
        int p = dir ? (valid ? (lenb - 1 - t) : t) : t;
        d_OUT[s][b][p][dir*HH + jh0 + j] = outv;
    }
}

// ---------------- row norms of encoder outputs ----------------
__global__ void norm_k()
{
    int wid  = (blockIdx.x * blockDim.x + threadIdx.x) >> 5;
    int lane = threadIdx.x & 31;
    if (wid >= 2*BB*LL) return;
    int s = wid >> 14, rem = wid & 16383, b = rem >> 9, l = rem & 511;
    const float* row = &d_OUT[s][b][l][0];
    float ss = 0.f;
    for (int k = lane; k < 2*HH; k += 32) { float v = row[k]; ss += v*v; }
#pragma unroll
    for (int off = 16; off; off >>= 1) ss += __shfl_down_sync(0xffffffffu, ss, off);
    if (lane == 0) d_NORM[s][b][l] = sqrtf(ss);
}

// ---------------- batched cosine-sim GEMM ----------------
__global__ void __launch_bounds__(256) sim_k()
{
    __shared__ float As[16][68];
    __shared__ float Bs[16][68];
    int b  = blockIdx.z;
    int n0 = blockIdx.x * 64;
    int m0 = blockIdx.y * 64;
    int t  = threadIdx.x;
    int lr = t >> 2;
    int kq = (t & 3) * 4;
    const float* Arow = &d_OUT[0][b][m0 + lr][0];
    const float* Brow = &d_OUT[1][b][n0 + lr][0];
    int tx = t & 15, ty = t >> 4;
    float acc[4][4] = {};
    for (int k0 = 0; k0 < 2*HH; k0 += 16) {
        float4 av = *(const float4*)(Arow + k0 + kq);
        float4 bv = *(const float4*)(Brow + k0 + kq);
        As[kq+0][lr] = av.x; As[kq+1][lr] = av.y; As[kq+2][lr] = av.z; As[kq+3][lr] = av.w;
        Bs[kq+0][lr] = bv.x; Bs[kq+1][lr] = bv.y; Bs[kq+2][lr] = bv.z; Bs[kq+3][lr] = bv.w;
        __syncthreads();
#pragma unroll
        for (int k = 0; k < 16; k++) {
            float a[4], bb[4];
#pragma unroll
            for (int i = 0; i < 4; i++) a[i]  = As[k][ty*4 + i];
#pragma unroll
            for (int j = 0; j < 4; j++) bb[j] = Bs[k][tx*4 + j];
#pragma unroll
            for (int i = 0; i < 4; i++)
#pragma unroll
                for (int j = 0; j < 4; j++)
                    acc[i][j] += a[i] * bb[j];
        }
        __syncthreads();
    }
    float n1[4], n2[4];
#pragma unroll
    for (int i = 0; i < 4; i++) n1[i] = d_NORM[0][b][m0 + ty*4 + i];
#pragma unroll
    for (int j = 0; j < 4; j++) n2[j] = d_NORM[1][b][n0 + tx*4 + j];
#pragma unroll
    for (int i = 0; i < 4; i++)
#pragma unroll
        for (int j = 0; j < 4; j++) {
            float den = fmaxf(n1[i] * n2[j], 1e-8f);
            d_SIM[b][m0 + ty*4 + i][n0 + tx*4 + j] = acc[i][j] / den;
        }
}

// ---------------- row max/argmax (first-index tie-break) ----------------
__global__ void rowmax_k()
{
    int wid  = blockIdx.x * 8 + (threadIdx.x >> 5);
    int lane = threadIdx.x & 31;
    int b = wid >> 9, i = wid & 511;
    float best = -INFINITY; int bidx = 0;
    for (int j = lane; j < LL; j += 32) {
        float v = d_SIM[b][i][j];
        if (v > best) { best = v; bidx = j; }
    }
#pragma unroll
    for (int off = 16; off; off >>= 1) {
        float ov = __shfl_down_sync(0xffffffffu, best, off);
        int   oi = __shfl_down_sync(0xffffffffu, bidx, off);
        if (ov > best || (ov == best && oi < bidx)) { best = ov; bidx = oi; }
    }
    if (lane == 0) {
        d_MS[0][b][i]  = best;
        d_REL[0][b][i] = (float)(i - bidx);
    }
}

// ---------------- col max/argmax ----------------
__global__ void colmax_k()
{
    int b = blockIdx.x;
    int j = threadIdx.x;
    float best = -INFINITY; int bidx = 0;
    for (int i = 0; i < LL; i++) {
        float v = d_SIM[b][i][j];
        if (v > best) { best = v; bidx = i; }
    }
    d_MS[1][b][j]  = best;
    d_REL[1][b][j] = (float)(j - bidx);
}

// ---------------- conv branches + BN + ReLU + maxpool + FC + softmax ----------------
__global__ void __launch_bounds__(128) head_k(const float* __restrict__ cw0,
                                              const float* __restrict__ cw1,
                                              const float* __restrict__ cw2,
                                              const float* __restrict__ cb,
                                              const float* __restrict__ bg,
                                              const float* __restrict__ bbeta,
                                              const float* __restrict__ bm,
                                              const float* __restrict__ bv,
                                              const float* __restrict__ fcw,
                                              const float* __restrict__ fcb,
                                              float* __restrict__ out)
{
    int b  = blockIdx.x;
    int ch = threadIdx.x;   // 128
    __shared__ float xs0[LL];
    __shared__ float xs1[LL];
    __shared__ float partial[128][2];
    float myfeat[6];
    for (int br = 0; br < 2; br++) {
        __syncthreads();
        for (int i = ch; i < LL; i += 128) {
            xs0[i] = d_MS[br][b][i];
            xs1[i] = d_REL[br][b][i];
        }
        __syncthreads();
        for (int ci = 0; ci < 3; ci++) {
            int K = 2 + ci;
            const float* cw = (ci == 0 ? cw0 : ci == 1 ? cw1 : cw2) + ch * 2 * K;
            float w0[4], w1[4];
            for (int q = 0; q < K; q++) { w0[q] = cw[q]; w1[q] = cw[K + q]; }
            float bias = cb[ci*128 + ch];
            float sc = bg[ci*128 + ch] * rsqrtf(bv[ci*128 + ch] + 1e-5f);
            float sh = bbeta[ci*128 + ch] - bm[ci*128 + ch] * sc;
            float best = -INFINITY;
            for (int p = 0; p + K <= LL; p++) {
                float acc = bias;
                for (int q = 0; q < K; q++)
                    acc += xs0[p+q]*w0[q] + xs1[p+q]*w1[q];
                float y = fmaxf(fmaf(acc, sc, sh), 0.f);
                best = fmaxf(best, y);
            }
            myfeat[br*3 + ci] = best;
        }
    }
    // FC: feature idx = br*384 + ci*128 + ch
    float p0 = 0.f, p1 = 0.f;
    for (int f = 0; f < 6; f++) {
        int idx = (f / 3) * 384 + (f % 3) * 128 + ch;
        p0 += myfeat[f] * fcw[idx];
        p1 += myfeat[f] * fcw[768 + idx];
    }
    partial[ch][0] = p0; partial[ch][1] = p1;
    __syncthreads();
    for (int st = 64; st; st >>= 1) {
        if (ch < st) {
            partial[ch][0] += partial[ch + st][0];
            partial[ch][1] += partial[ch + st][1];
        }
        __syncthreads();
    }
    if (ch == 0) {
        float l0 = partial[0][0] + fcb[0];
        float l1 = partial[0][1] + fcb[1];
        float m  = fmaxf(l0, l1);
        float e0 = expf(l0 - m), e1 = expf(l1 - m);
        float sinv = 1.f / (e0 + e1);
        out[b*2 + 0] = e0 * sinv;
        out[b*2 + 1] = e1 * sinv;
    }
}

// ---------------- launcher ----------------
extern "C" void kernel_launch(void* const* d_in, const int* in_sizes, int n_in,
                              void* d_out, int out_size)
{
    const int*   w1   = (const int*)  d_in[0];
    const int*   w2   = (const int*)  d_in[1];
    const int*   p1   = (const int*)  d_in[2];
    const int*   p2   = (const int*)  d_in[3];
    const int*   len1 = (const int*)  d_in[4];
    const int*   len2 = (const int*)  d_in[5];
    const int*   tb1  = (const int*)  d_in[6];
    const int*   te1  = (const int*)  d_in[7];
    const int*   tb2  = (const int*)  d_in[8];
    const int*   te2  = (const int*)  d_in[9];
    const float* ew   = (const float*)d_in[10];
    const float* ep   = (const float*)d_in[11];
    const float* pe   = (const float*)d_in[12];
    const float* wih  = (const float*)d_in[13];
    const float* whh  = (const float*)d_in[14];
    const float* bih  = (const float*)d_in[15];
    const float* bhh  = (const float*)d_in[16];
    const float* cw0  = (const float*)d_in[17];
    const float* cw1  = (const float*)d_in[18];
    const float* cw2  = (const float*)d_in[19];
    const float* cb   = (const float*)d_in[20];
    const float* bg   = (const float*)d_in[21];
    const float* bbta = (const float*)d_in[22];
    const float* bm   = (const float*)d_in[23];
    const float* bvv  = (const float*)d_in[24];
    const float* fcw  = (const float*)d_in[25];
    const float* fcb  = (const float*)d_in[26];
    float* out = (float*)d_out;

    void* haddr = nullptr;
    cudaGetSymbolAddress(&haddr, d_Hb);
    cudaMemsetAsync(haddr, 0, sizeof(float) * 2 * 4 * BB * HH);

    embed_k<<<2*BB*LL, 256>>>(w1, w2, p1, p2, tb1, te1, tb2, te2, ew, ep, pe);
    gemm_gi_k<<<dim3(G3/64, (BB*LL)/64, 4), 256>>>(wih, bih, len1, len2);
    for (int t = 0; t < LL; t++)
        gru_step_k<<<dim3(HH/TH, 4), 384>>>(t, t & 1, whh, bhh, len1, len2);
    norm_k<<<(2*BB*LL)/8, 256>>>();
    sim_k<<<dim3(LL/64, LL/64, BB), 256>>>();
    rowmax_k<<<(BB*LL)/8, 256>>>();
    colmax_k<<<BB, LL>>>();
    head_k<<<BB, 128>>>(cw0, cw1, cw2, cb, bg, bbta, bm, bvv, fcw, fcb, out);
}

// round 16
// speedup vs baseline: 2.0160x; 2.0160x over previous
#include <cuda_runtime.h>
#include <math.h>

#define BB   32
#define LL   512
#define HH   512
#define DIN  832
#define G3   1536
#define DPOS 64
#define TH   16
#define NBLK 128
#define WS_STRIDE 520   // padded row stride for Whh slice in SMEM (bank-conflict-free)

// ---------------- scratch (static device globals; no allocation) ----------------
__device__ float d_X[2][BB][LL][DIN];
__device__ float d_GI[4][BB][LL][G3];
__device__ float d_Hb[2][4][BB][HH];
__device__ float d_OUT[2][BB][LL][2*HH];
__device__ float d_SIM[BB][LL][LL];
__device__ float d_NORM[2][BB][LL];
__device__ float d_MS[2][BB][LL];
__device__ float d_REL[2][BB][LL];
__device__ int   g_bar[NBLK + 1];      // [0..127] arrive gens, [128] release gen

// ---------------- embedding concat ----------------
__global__ void embed_k(const int* __restrict__ w1, const int* __restrict__ w2,
                        const int* __restrict__ p1, const int* __restrict__ p2,
                        const int* __restrict__ tb1, const int* __restrict__ te1,
                        const int* __restrict__ tb2, const int* __restrict__ te2,
                        const float* __restrict__ ew, const float* __restrict__ ep,
                        const float* __restrict__ pe)
{
    int gid = blockIdx.x;
    int s   = gid >> 14;
    int rem = gid & 16383;
    int b   = rem >> 9;
    int l   = rem & 511;
    const int* wp  = s ? w2  : w1;
    const int* pp  = s ? p2  : p1;
    const int* tbp = s ? tb2 : tb1;
    const int* tep = s ? te2 : te1;
    int wi = wp[b*LL + l];
    int pi = pp[b*LL + l];
    int tb = tbp[b*LL + l];
    int te = tep[b*LL + l];
    float* dst = &d_X[s][b][l][0];
    for (int d = threadIdx.x; d < DIN; d += blockDim.x) {
        float v;
        if      (d < 256) v = ew[wi*256 + d];
        else if (d < 512) v = ep[pi*256 + (d-256)];
        else if (d < 576) v = pe[l*DPOS      + (d-512)];
        else if (d < 640) v = pe[tb*DPOS     + (d-576)];
        else if (d < 704) v = pe[te*DPOS     + (d-640)];
        else if (d < 768) v = pe[(te-l)*DPOS + (d-704)];
        else              v = pe[(l-tb)*DPOS + (d-768)];
        dst[d] = v;
    }
}

// ---------------- input GEMM ----------------
__global__ void __launch_bounds__(256) gemm_gi_k(const float* __restrict__ Wih,
                                                 const float* __restrict__ bih,
                                                 const int* __restrict__ len1,
                                                 const int* __restrict__ len2)
{
    __shared__ float As[16][68];
    __shared__ float Bs[16][68];
    int sd  = blockIdx.z;
    int s   = sd >> 1, dir = sd & 1;
    int n0  = blockIdx.x * 64;
    int m0  = blockIdx.y * 64;
    int b   = m0 >> 9;
    int lenb = (s == 0 ? len1 : len2)[b];
    int t   = threadIdx.x;
    int lr  = t >> 2;
    int kq  = (t & 3) * 4;
    int l   = (m0 & 511) + lr;
    int lp  = l;
    if (dir) lp = (l < lenb) ? (lenb - 1 - l) : l;
    const float* Arow = &d_X[s][b][lp][0];
    const float* Brow = Wih + (size_t)(dir*G3 + n0 + lr) * DIN;
    int tx = t & 15, ty = t >> 4;
    float acc[4][4] = {};
    for (int k0 = 0; k0 < DIN; k0 += 16) {
        float4 av = *(const float4*)(Arow + k0 + kq);
        float4 bv = *(const float4*)(Brow + k0 + kq);
        As[kq+0][lr] = av.x; As[kq+1][lr] = av.y; As[kq+2][lr] = av.z; As[kq+3][lr] = av.w;
        Bs[kq+0][lr] = bv.x; Bs[kq+1][lr] = bv.y; Bs[kq+2][lr] = bv.z; Bs[kq+3][lr] = bv.w;
        __syncthreads();
#pragma unroll
        for (int k = 0; k < 16; k++) {
            float a[4], bb[4];
#pragma unroll
            for (int i = 0; i < 4; i++) a[i]  = As[k][ty*4 + i];
#pragma unroll
            for (int j = 0; j < 4; j++) bb[j] = Bs[k][tx*4 + j];
#pragma unroll
            for (int i = 0; i < 4; i++)
#pragma unroll
                for (int j = 0; j < 4; j++)
                    acc[i][j] += a[i] * bb[j];
        }
        __syncthreads();
    }
    int c = s*2 + dir;
#pragma unroll
    for (int i = 0; i < 4; i++) {
        int ll = (m0 & 511) + ty*4 + i;
#pragma unroll
        for (int j = 0; j < 4; j++) {
            int g = n0 + tx*4 + j;
            d_GI[c][b][ll][g] = acc[i][j] + bih[dir*G3 + g];
        }
    }
}

// ---------------- grid barrier (all NBLK blocks co-resident by construction) ----------------
__device__ __forceinline__ void grid_bar(int bid, int gen)
{
    __syncthreads();
    if (threadIdx.x == 0) {
        __threadfence();
        *(volatile int*)&g_bar[bid] = gen;
    }
    if (bid == 0) {
        if (threadIdx.x < NBLK) {
            while (*(volatile int*)&g_bar[threadIdx.x] < gen) { }
        }
        __syncthreads();
        if (threadIdx.x == 0) {
            __threadfence();
            *(volatile int*)&g_bar[NBLK] = gen;
        }
    } else {
        if (threadIdx.x == 0) {
            while (*(volatile int*)&g_bar[NBLK] < gen) { }
        }
    }
    __syncthreads();
}

// ---------------- persistent GRU recurrence: all 512 steps in one kernel ----------------
// 128 blocks = 4 chains x 32 hidden tiles (TH=16). Whh slice SMEM-resident.
__global__ void __launch_bounds__(384, 1) gru_persist_k(
    const float* __restrict__ Whh, const float* __restrict__ bhh,
    const int* __restrict__ len1, const int* __restrict__ len2)
{
    extern __shared__ float smem[];
    float* ws = smem;                        // [48][WS_STRIDE]
    float* hs = smem + 48*WS_STRIDE;         // [512][32]  (k-major, hs[k*32+b])
    float* gh = hs + 512*32;                 // [48][32]

    const int bid  = blockIdx.x;
    const int c    = bid & 3;                // chain
    const int tile = bid >> 2;               // 0..31
    const int jh0  = tile * TH;
    const int s    = c >> 1, dir = c & 1;
    const int tid  = threadIdx.x;
    const int g_local = tid >> 3;            // 0..47
    const int bbase   = (tid & 7) * 4;       // 4 batches per thread

    // Load this block's 48x512 Whh slice into SMEM once.
    for (int i = tid; i < 48*128; i += 384) {
        int row = i >> 7, k4 = i & 127;
        int grow = (row/TH)*HH + jh0 + (row%TH);
        float4 v = *(const float4*)(Whh + (size_t)(dir*G3 + grow)*HH + k4*4);
        *(float4*)&ws[row*WS_STRIDE + k4*4] = v;
    }
    const int*   lenp = (s == 0) ? len1 : len2;
    const float* bh   = bhh + dir*G3;

    // epilogue item mapping: item i -> b = i&31, j = i>>5  (512 items; tid and tid+384)
    const int b0 = tid & 31,          j0 = tid >> 5;
    const int b1 = (tid + 384) & 31,  j1 = (tid + 384) >> 5;
    const bool has1 = (tid < 128);
    const float bhr0 = bh[jh0 + j0],      bhz0 = bh[HH + jh0 + j0],      bhn0 = bh[2*HH + jh0 + j0];
    const float bhr1 = bh[jh0 + j1],      bhz1 = bh[HH + jh0 + j1],      bhn1 = bh[2*HH + jh0 + j1];
    const int len0 = lenp[b0], len1v = lenp[b1];

    for (int t = 0; t < LL; t++) {
        const int par = t & 1;
        // prefetch gi for this step's epilogue (hidden under staging + gemv)
        const float* gi0 = &d_GI[c][b0][t][0];
        float gir0 = gi0[jh0 + j0], giz0 = gi0[HH + jh0 + j0], gin0 = gi0[2*HH + jh0 + j0];
        float gir1 = 0.f, giz1 = 0.f, gin1 = 0.f;
        if (has1) {
            const float* gi1 = &d_GI[c][b1][t][0];
            gir1 = gi1[jh0 + j1]; giz1 = gi1[HH + jh0 + j1]; gin1 = gi1[2*HH + jh0 + j1];
        }
        // stage h_t (L1-bypass: other blocks wrote it; L1 is stale across grid barrier)
        for (int i = tid; i < 4096; i += 384) {
            int k4 = i >> 5, b = i & 31;
            float4 v = __ldcg((const float4*)&d_Hb[par][c][b][k4*4]);
            hs[(4*k4+0)*32 + b] = v.x;
            hs[(4*k4+1)*32 + b] = v.y;
            hs[(4*k4+2)*32 + b] = v.z;
            hs[(4*k4+3)*32 + b] = v.w;
        }
        __syncthreads();
        // gemv: gh[g][b] = sum_k ws[g][k] * h[k][b]
        float a0 = 0.f, a1 = 0.f, a2 = 0.f, a3 = 0.f;
        const float* wrow = &ws[g_local*WS_STRIDE];
#pragma unroll 8
        for (int k = 0; k < 512; k++) {
            float w = wrow[k];
            float4 h4 = *(const float4*)&hs[k*32 + bbase];
            a0 += w * h4.x; a1 += w * h4.y; a2 += w * h4.z; a3 += w * h4.w;
        }
        gh[g_local*32 + bbase + 0] = a0;
        gh[g_local*32 + bbase + 1] = a1;
        gh[g_local*32 + bbase + 2] = a2;
        gh[g_local*32 + bbase + 3] = a3;
        __syncthreads();
        // epilogue: gates + freeze + scatter
        {
            float hr = gh[j0*32 + b0] + bhr0;
            float hz = gh[(TH + j0)*32 + b0] + bhz0;
            float hn = gh[(2*TH + j0)*32 + b0] + bhn0;
            float r = 1.f / (1.f + expf(-(gir0 + hr)));
            float z = 1.f / (1.f + expf(-(giz0 + hz)));
            float n = tanhf(gin0 + r * hn);
            float hold = hs[(jh0 + j0)*32 + b0];
            float hc   = (1.f - z) * n + z * hold;
            bool valid = (t < len0);
            d_Hb[par ^ 1][c][b0][jh0 + j0] = valid ? hc : hold;
            int p = dir ? (valid ? (len0 - 1 - t) : t) : t;
            d_OUT[s][b0][p][dir*HH + jh0 + j0] = valid ? hc : 0.f;
        }
        if (has1) {
            float hr = gh[j1*32 + b1] + bhr1;
            float hz = gh[(TH + j1)*32 + b1] + bhz1;
            float hn = gh[(2*TH + j1)*32 + b1] + bhn1;
            float r = 1.f / (1.f + expf(-(gir1 + hr)));
            float z = 1.f / (1.f + expf(-(giz1 + hz)));
            float n = tanhf(gin1 + r * hn);
            float hold = hs[(jh0 + j1)*32 + b1];
            float hc   = (1.f - z) * n + z * hold;
            bool valid = (t < len1v);
            d_Hb[par ^ 1][c][b1][jh0 + j1] = valid ? hc : hold;
            int p = dir ? (valid ? (len1v - 1 - t) : t) : t;
            d_OUT[s][b1][p][dir*HH + jh0 + j1] = valid ? hc : 0.f;
        }
        grid_bar(bid, t + 1);
    }
}

// ---------------- row norms ----------------
__global__ void norm_k()
{
    int wid  = (blockIdx.x * blockDim.x + threadIdx.x) >> 5;
    int lane = threadIdx.x & 31;
    if (wid >= 2*BB*LL) return;
    int s = wid >> 14, rem = wid & 16383, b = rem >> 9, l = rem & 511;
    const float* row = &d_OUT[s][b][l][0];
    float ss = 0.f;
    for (int k = lane; k < 2*HH; k += 32) { float v = row[k]; ss += v*v; }
#pragma unroll
    for (int off = 16; off; off >>= 1) ss += __shfl_down_sync(0xffffffffu, ss, off);
    if (lane == 0) d_NORM[s][b][l] = sqrtf(ss);
}

// ---------------- batched cosine-sim GEMM ----------------
__global__ void __launch_bounds__(256) sim_k()
{
    __shared__ float As[16][68];
    __shared__ float Bs[16][68];
    int b  = blockIdx.z;
    int n0 = blockIdx.x * 64;
    int m0 = blockIdx.y * 64;
    int t  = threadIdx.x;
    int lr = t >> 2;
    int kq = (t & 3) * 4;
    const float* Arow = &d_OUT[0][b][m0 + lr][0];
    const float* Brow = &d_OUT[1][b][n0 + lr][0];
    int tx = t & 15, ty = t >> 4;
    float acc[4][4] = {};
    for (int k0 = 0; k0 < 2*HH; k0 += 16) {
        float4 av = *(const float4*)(Arow + k0 + kq);
        float4 bv = *(const float4*)(Brow + k0 + kq);
        As[kq+0][lr] = av.x; As[kq+1][lr] = av.y; As[kq+2][lr] = av.z; As[kq+3][lr] = av.w;
        Bs[kq+0][lr] = bv.x; Bs[kq+1][lr] = bv.y; Bs[kq+2][lr] = bv.z; Bs[kq+3][lr] = bv.w;
        __syncthreads();
#pragma unroll
        for (int k = 0; k < 16; k++) {
            float a[4], bb[4];
#pragma unroll
            for (int i = 0; i < 4; i++) a[i]  = As[k][ty*4 + i];
#pragma unroll
            for (int j = 0; j < 4; j++) bb[j] = Bs[k][tx*4 + j];
#pragma unroll
            for (int i = 0; i < 4; i++)
#pragma unroll
                for (int j = 0; j < 4; j++)
                    acc[i][j] += a[i] * bb[j];
        }
        __syncthreads();
    }
    float n1[4], n2[4];
#pragma unroll
    for (int i = 0; i < 4; i++) n1[i] = d_NORM[0][b][m0 + ty*4 + i];
#pragma unroll
    for (int j = 0; j < 4; j++) n2[j] = d_NORM[1][b][n0 + tx*4 + j];
#pragma unroll
    for (int i = 0; i < 4; i++)
#pragma unroll
        for (int j = 0; j < 4; j++) {
            float den = fmaxf(n1[i] * n2[j], 1e-8f);
            d_SIM[b][m0 + ty*4 + i][n0 + tx*4 + j] = acc[i][j] / den;
        }
}

// ---------------- row max/argmax ----------------
__global__ void rowmax_k()
{
    int wid  = blockIdx.x * 8 + (threadIdx.x >> 5);
    int lane = threadIdx.x & 31;
    int b = wid >> 9, i = wid & 511;
    float best = -INFINITY; int bidx = 0;
    for (int j = lane; j < LL; j += 32) {
        float v = d_SIM[b][i][j];
        if (v > best) { best = v; bidx = j; }
    }
#pragma unroll
    for (int off = 16; off; off >>= 1) {
        float ov = __shfl_down_sync(0xffffffffu, best, off);
        int   oi = __shfl_down_sync(0xffffffffu, bidx, off);
        if (ov > best || (ov == best && oi < bidx)) { best = ov; bidx = oi; }
    }
    if (lane == 0) {
        d_MS[0][b][i]  = best;
        d_REL[0][b][i] = (float)(i - bidx);
    }
}

// ---------------- col max/argmax ----------------
__global__ void colmax_k()
{
    int b = blockIdx.x;
    int j = threadIdx.x;
    float best = -INFINITY; int bidx = 0;
    for (int i = 0; i < LL; i++) {
        float v = d_SIM[b][i][j];
        if (v > best) { best = v; bidx = i; }
    }
    d_MS[1][b][j]  = best;
    d_REL[1][b][j] = (float)(j - bidx);
}

// ---------------- head ----------------
__global__ void __launch_bounds__(128) head_k(const float* __restrict__ cw0,
                                              const float* __restrict__ cw1,
                                              const float* __restrict__ cw2,
                                              const float* __restrict__ cb,
                                              const float* __restrict__ bg,
                                              const float* __restrict__ bbeta,
                                              const float* __restrict__ bm,
                                              const float* __restrict__ bv,
                                              const float* __restrict__ fcw,
                                              const float* __restrict__ fcb,
                                              float* __restrict__ out)
{
    int b  = blockIdx.x;
    int ch = threadIdx.x;
    __shared__ float xs0[LL];
    __shared__ float xs1[LL];
    __shared__ float partial[128][2];
    float myfeat[6];
    for (int br = 0; br < 2; br++) {
        __syncthreads();
        for (int i = ch; i < LL; i += 128) {
            xs0[i] = d_MS[br][b][i];
            xs1[i] = d_REL[br][b][i];
        }
        __syncthreads();
        for (int ci = 0; ci < 3; ci++) {
            int K = 2 + ci;
            const float* cw = (ci == 0 ? cw0 : ci == 1 ? cw1 : cw2) + ch * 2 * K;
            float w0[4], w1[4];
            for (int q = 0; q < K; q++) { w0[q] = cw[q]; w1[q] = cw[K + q]; }
            float bias = cb[ci*128 + ch];
            float sc = bg[ci*128 + ch] * rsqrtf(bv[ci*128 + ch] + 1e-5f);
            float sh = bbeta[ci*128 + ch] - bm[ci*128 + ch] * sc;
            float best = -INFINITY;
            for (int p = 0; p + K <= LL; p++) {
                float acc = bias;
                for (int q = 0; q < K; q++)
                    acc += xs0[p+q]*w0[q] + xs1[p+q]*w1[q];
                float y = fmaxf(fmaf(acc, sc, sh), 0.f);
                best = fmaxf(best, y);
            }
            myfeat[br*3 + ci] = best;
        }
    }
    float p0 = 0.f, p1 = 0.f;
    for (int f = 0; f < 6; f++) {
        int idx = (f / 3) * 384 + (f % 3) * 128 + ch;
        p0 += myfeat[f] * fcw[idx];
        p1 += myfeat[f] * fcw[768 + idx];
    }
    partial[ch][0] = p0; partial[ch][1] = p1;
    __syncthreads();
    for (int st = 64; st; st >>= 1) {
        if (ch < st) {
            partial[ch][0] += partial[ch + st][0];
            partial[ch][1] += partial[ch + st][1];
        }
        __syncthreads();
    }
    if (ch == 0) {
        float l0 = partial[0][0] + fcb[0];
        float l1 = partial[0][1] + fcb[1];
        float m  = fmaxf(l0, l1);
        float e0 = expf(l0 - m), e1 = expf(l1 - m);
        float sinv = 1.f / (e0 + e1);
        out[b*2 + 0] = e0 * sinv;
        out[b*2 + 1] = e1 * sinv;
    }
}

// ---------------- launcher ----------------
extern "C" void kernel_launch(void* const* d_in, const int* in_sizes, int n_in,
                              void* d_out, int out_size)
{
    const int*   w1   = (const int*)  d_in[0];
    const int*   w2   = (const int*)  d_in[1];
    const int*   p1   = (const int*)  d_in[2];
    const int*   p2   = (const int*)  d_in[3];
    const int*   len1 = (const int*)  d_in[4];
    const int*   len2 = (const int*)  d_in[5];
    const int*   tb1  = (const int*)  d_in[6];
    const int*   te1  = (const int*)  d_in[7];
    const int*   tb2  = (const int*)  d_in[8];
    const int*   te2  = (const int*)  d_in[9];
    const float* ew   = (const float*)d_in[10];
    const float* ep   = (const float*)d_in[11];
    const float* pe   = (const float*)d_in[12];
    const float* wih  = (const float*)d_in[13];
    const float* whh  = (const float*)d_in[14];
    const float* bih  = (const float*)d_in[15];
    const float* bhh  = (const float*)d_in[16];
    const float* cw0  = (const float*)d_in[17];
    const float* cw1  = (const float*)d_in[18];
    const float* cw2  = (const float*)d_in[19];
    const float* cb   = (const float*)d_in[20];
    const float* bg   = (const float*)d_in[21];
    const float* bbta = (const float*)d_in[22];
    const float* bm   = (const float*)d_in[23];
    const float* bvv  = (const float*)d_in[24];
    const float* fcw  = (const float*)d_in[25];
    const float* fcb  = (const float*)d_in[26];
    float* out = (float*)d_out;

    const int SMEM_BYTES = (48*WS_STRIDE + 512*32 + 48*32) * 4;  // 171,520 B
    cudaFuncSetAttribute(gru_persist_k, cudaFuncAttributeMaxDynamicSharedMemorySize, SMEM_BYTES);

    void* haddr = nullptr;
    cudaGetSymbolAddress(&haddr, d_Hb);
    cudaMemsetAsync(haddr, 0, sizeof(float) * 2 * 4 * BB * HH);
    void* baddr = nullptr;
    cudaGetSymbolAddress(&baddr, g_bar);
    cudaMemsetAsync(baddr, 0, sizeof(int) * (NBLK + 1));

    embed_k<<<2*BB*LL, 256>>>(w1, w2, p1, p2, tb1, te1, tb2, te2, ew, ep, pe);
    gemm_gi_k<<<dim3(G3/64, (BB*LL)/64, 4), 256>>>(wih, bih, len1, len2);
    gru_persist_k<<<NBLK, 384, SMEM_BYTES>>>(whh, bhh, len1, len2);
    norm_k<<<(2*BB*LL)/8, 256>>>();
    sim_k<<<dim3(LL/64, LL/64, BB), 256>>>();
    rowmax_k<<<(BB*LL)/8, 256>>>();
    colmax_k<<<BB, LL>>>();
    head_k<<<BB, 128>>>(cw0, cw1, cw2, cb, bg, bbta, bm, bvv, fcw, fcb, out);
}